// round 13
// baseline (speedup 1.0000x reference)
#include <cuda_runtime.h>
#include <cuda_fp16.h>
#include <cstdint>

// Problem shape (fixed)
#define D_M 8192
#define D_N 4096
#define D_K 4096

// GEMM tiling: CTA 128x128, 4 warps (2m x 2n), warp tile 64x64, 2 CTAs/SM
#define TM 128
#define TN 128
#define KS 64                 // K per smem stage
#define KT (D_K / KS)         // 64
#define NMT (D_M / TM)        // 64
#define NNT (D_N / TN)        // 32
#define STAGES 3
#define NTHREADS 128

// fp16 scratch (static device globals: no runtime allocation)
__device__ __half g_A[(size_t)D_M * D_K];   // [M][K]
__device__ __half g_B[(size_t)D_K * D_N];   // [K][N]  (W transposed)

// ---------------- smem layout (per CTA ~99KB so 2 CTAs/SM fit) ----------------
#define A_STAGE (TM * KS * 2)                 // 16384 (128 rows x 128B)
#define B_STAGE (KS * TN * 2)                 // 16384 (64 rows x 256B)
#define SA_OFF 0
#define SB_OFF (STAGES * A_STAGE)             // 49152
#define SCALE_OFF (SB_OFF + STAGES * B_STAGE) // 98304
#define BIAS_OFF (SCALE_OFF + TN * 4)         // 98816
#define SMEM_TOTAL (BIAS_OFF + TN * 4)        // 99328 (x2 = 198656 < 228KB)

// ---------------- helpers ----------------
__device__ __forceinline__ uint32_t smem_u32(const void* p) {
    uint32_t r;
    asm("{ .reg .u64 t; cvta.to.shared.u64 t, %1; cvt.u32.u64 %0, t; }"
        : "=r"(r) : "l"(p));
    return r;
}

__device__ __forceinline__ void cp_async16(uint32_t dst, const void* src) {
    asm volatile("cp.async.cg.shared.global [%0], [%1], 16;"
                 :: "r"(dst), "l"(src));
}

__device__ __forceinline__ void ldsm_x4(uint32_t (&r)[4], uint32_t addr) {
    asm volatile("ldmatrix.sync.aligned.m8n8.x4.shared.b16 {%0,%1,%2,%3}, [%4];"
                 : "=r"(r[0]), "=r"(r[1]), "=r"(r[2]), "=r"(r[3]) : "r"(addr));
}

__device__ __forceinline__ void ldsm_x4_t(uint32_t (&r)[4], uint32_t addr) {
    asm volatile("ldmatrix.sync.aligned.m8n8.x4.trans.shared.b16 {%0,%1,%2,%3}, [%4];"
                 : "=r"(r[0]), "=r"(r[1]), "=r"(r[2]), "=r"(r[3]) : "r"(addr));
}

__device__ __forceinline__ void mma16816(float (&d)[4], const uint32_t (&a)[4],
                                         uint32_t b0, uint32_t b1) {
    asm volatile(
        "mma.sync.aligned.m16n8k16.row.col.f32.f16.f16.f32 "
        "{%0,%1,%2,%3},{%4,%5,%6,%7},{%8,%9},{%0,%1,%2,%3};"
        : "+f"(d[0]), "+f"(d[1]), "+f"(d[2]), "+f"(d[3])
        : "r"(a[0]), "r"(a[1]), "r"(a[2]), "r"(a[3]), "r"(b0), "r"(b1));
}

// ---------------- fused prepass ----------------
// Blocks [0, XB): convert x fp32 -> g_A fp16 (2 float4 per thread)
// Blocks [XB, XB+WB): transpose W [N][K] int32 -> g_B [K][N] fp16
#define XB 16384   // (8192*4096/4 float4) / (256 thr * 2)
#define WB ((D_K / 32) * (D_N / 32))   // 16384

struct alignas(8) H4 { __half2 a, b; };

__global__ void __launch_bounds__(256)
prepass_kernel(const float4* __restrict__ x, const int* __restrict__ w) {
    int b = blockIdx.x;
    if (b < XB) {
        size_t base = (size_t)b * 512 + threadIdx.x;
        float4 v0 = x[base];
        float4 v1 = x[base + 256];
        H4 h0, h1;
        h0.a = __floats2half2_rn(v0.x, v0.y);
        h0.b = __floats2half2_rn(v0.z, v0.w);
        h1.a = __floats2half2_rn(v1.x, v1.y);
        h1.b = __floats2half2_rn(v1.z, v1.w);
        reinterpret_cast<H4*>(g_A)[base] = h0;
        reinterpret_cast<H4*>(g_A)[base + 256] = h1;
    } else {
        __shared__ __half s[32][33];
        int wb = b - XB;
        int tx = threadIdx.x & 31, ty = threadIdx.x >> 5;   // 32 x 8
        int k0 = (wb & (D_K / 32 - 1)) * 32;
        int n0 = (wb / (D_K / 32)) * 32;
#pragma unroll
        for (int r = 0; r < 4; r++) {
            int n = ty + 8 * r;
            s[tx][n] = __int2half_rn(w[(size_t)(n0 + n) * D_K + k0 + tx]);
        }
        __syncthreads();
#pragma unroll
        for (int r = 0; r < 4; r++) {
            int k = ty + 8 * r;
            g_B[(size_t)(k0 + k) * D_N + n0 + tx] = s[k][tx];
        }
    }
}

// ---------------- stage loaders ----------------
// A smem: [m row 0..127][8 chunks of 16B], chunk' = c ^ (m&7)
// B smem: [k row 0..63][16 chunks of 16B], chunk' = (c&~7)|((c&7)^(k&7))
__device__ __forceinline__ void load_stage(int kt, int tid, uint32_t sbase,
                                           const __half* Ag, const __half* Bg) {
    int slot = kt % STAGES;
    uint32_t sa = sbase + SA_OFF + slot * A_STAGE;
    uint32_t sb = sbase + SB_OFF + slot * B_STAGE;
#pragma unroll
    for (int it = 0; it < 8; it++) {
        int idx = tid + it * NTHREADS;       // 0..1023
        int row = idx >> 3, c = idx & 7;
        const void* src = Ag + (size_t)row * D_K + kt * KS + c * 8;
        uint32_t dst = sa + row * 128 + ((c ^ (row & 7)) << 4);
        cp_async16(dst, src);
    }
#pragma unroll
    for (int it = 0; it < 8; it++) {
        int idx = tid + it * NTHREADS;       // 0..1023
        int kr = idx >> 4, c = idx & 15;
        const void* src = Bg + (size_t)(kt * KS + kr) * D_N + c * 8;
        int cs = (c & ~7) | ((c & 7) ^ (kr & 7));
        uint32_t dst = sb + kr * 256 + (cs << 4);
        cp_async16(dst, src);
    }
    asm volatile("cp.async.commit_group;" ::: "memory");
}

// one quarter of a stage (2 A + 2 B cp.asyncs per thread), no commit
__device__ __forceinline__ void load_quarter(int kt, int q, int tid, uint32_t sbase,
                                             const __half* Ag, const __half* Bg) {
    int slot = kt % STAGES;
    uint32_t sa = sbase + SA_OFF + slot * A_STAGE;
    uint32_t sb = sbase + SB_OFF + slot * B_STAGE;
#pragma unroll
    for (int it = 2 * q; it < 2 * q + 2; it++) {
        int idx = tid + it * NTHREADS;
        int row = idx >> 3, c = idx & 7;
        const void* src = Ag + (size_t)row * D_K + kt * KS + c * 8;
        uint32_t dst = sa + row * 128 + ((c ^ (row & 7)) << 4);
        cp_async16(dst, src);
    }
#pragma unroll
    for (int it = 2 * q; it < 2 * q + 2; it++) {
        int idx = tid + it * NTHREADS;
        int kr = idx >> 4, c = idx & 15;
        const void* src = Bg + (size_t)(kt * KS + kr) * D_N + c * 8;
        int cs = (c & ~7) | ((c & 7) ^ (kr & 7));
        uint32_t dst = sb + kr * 256 + (cs << 4);
        cp_async16(dst, src);
    }
}

// ---------------- GEMM kernel ----------------
__global__ void __launch_bounds__(NTHREADS, 2)
gemm_kernel(const float* __restrict__ scale, const float* __restrict__ bias,
            float* __restrict__ out) {
    extern __shared__ __align__(1024) char smem[];
    uint32_t sbase = smem_u32(smem);
    int tid = threadIdx.x, wid = tid >> 5, lane = tid & 31;

    // tile rasterization: supergroups of 8 M-tiles x 32 N-tiles (L2 reuse)
    int bid = blockIdx.x;
    const int G = 8, per = G * NNT;          // 256
    int g = bid / per, r = bid % per;
    int mt = g * G + (r % G);
    int nt = r / G;
    int mbase = mt * TM, nbase = nt * TN;

    const __half* Ag = g_A + (size_t)mbase * D_K;
    const __half* Bg = g_B + nbase;

    // scale/bias preload
    float* ss = (float*)(smem + SCALE_OFF);
    float* bb = (float*)(smem + BIAS_OFF);
    for (int i = tid; i < TN; i += NTHREADS) {
        ss[i] = scale[nbase + i];
        bb[i] = bias[nbase + i];
    }

    // prologue: first STAGES-1 stages in flight
    for (int s = 0; s < STAGES - 1; s++) load_stage(s, tid, sbase, Ag, Bg);

    int wm = (wid & 1) * 64;     // warp m offset (2 m-warps)
    int wn = (wid >> 1) * 64;    // warp n offset (2 n-warps)

    float acc[4][8][4];
#pragma unroll
    for (int i = 0; i < 4; i++)
#pragma unroll
        for (int j = 0; j < 8; j++)
#pragma unroll
            for (int q = 0; q < 4; q++) acc[i][j][q] = 0.f;

    for (int kt = 0; kt < KT; kt++) {
        asm volatile("cp.async.wait_group %0;" :: "n"(STAGES - 2) : "memory");
        __syncthreads();

        int lt = kt + STAGES - 1;
        bool dl = (lt < KT);

        int slot = kt % STAGES;
        uint32_t sa = sbase + SA_OFF + slot * A_STAGE;
        uint32_t sb = sbase + SB_OFF + slot * B_STAGE;

#pragma unroll
        for (int s16 = 0; s16 < 4; s16++) {
            uint32_t a[4][4], b[4][4];
            // B LDSMs first: consumed by the first MMAs, give them max latency overlap
            int bk = s16 * 16 + (lane & 15);
#pragma unroll
            for (int ni = 0; ni < 4; ni++) {
                int chunk = (wn >> 3) + 2 * ni + (lane >> 4);
                int cs = (chunk & ~7) | ((chunk & 7) ^ (bk & 7));
                ldsm_x4_t(b[ni], sb + bk * 256 + (cs << 4));
            }
            int arow = wm + (lane & 15);
            int achunk = s16 * 2 + (lane >> 4);
#pragma unroll
            for (int mi = 0; mi < 4; mi++) {
                int rr = arow + mi * 16;
                ldsm_x4(a[mi], sa + rr * 128 + ((achunk ^ (rr & 7)) << 4));
            }
            // first 8 MMAs (mi = 0) start the tensor pipe
#pragma unroll
            for (int ni = 0; ni < 4; ni++) {
                mma16816(acc[0][2 * ni],     a[0], b[ni][0], b[ni][1]);
                mma16816(acc[0][2 * ni + 1], a[0], b[ni][2], b[ni][3]);
            }
            // cp.async burst after the pipe is fed
            if (dl) load_quarter(lt, s16, tid, sbase, Ag, Bg);
            // remaining 24 MMAs
#pragma unroll
            for (int mi = 1; mi < 4; mi++)
#pragma unroll
                for (int ni = 0; ni < 4; ni++) {
                    mma16816(acc[mi][2 * ni],     a[mi], b[ni][0], b[ni][1]);
                    mma16816(acc[mi][2 * ni + 1], a[mi], b[ni][2], b[ni][3]);
                }
        }
        asm volatile("cp.async.commit_group;" ::: "memory");
    }

    // epilogue: scale + bias fused, float2 stores
    int qr = lane >> 2, qc = lane & 3;
#pragma unroll
    for (int mi = 0; mi < 4; mi++) {
        int row0 = mbase + wm + mi * 16 + qr;
#pragma unroll
        for (int nj = 0; nj < 8; nj++) {
            int col = wn + nj * 8 + 2 * qc;
            float2 sc = *(const float2*)(ss + col);
            float2 bv = *(const float2*)(bb + col);
            float* p0 = out + (size_t)row0 * D_N + nbase + col;
            float* p1 = p0 + 8 * (size_t)D_N;
            float2 v0, v1;
            v0.x = acc[mi][nj][0] * sc.x + bv.x;
            v0.y = acc[mi][nj][1] * sc.y + bv.y;
            v1.x = acc[mi][nj][2] * sc.x + bv.x;
            v1.y = acc[mi][nj][3] * sc.y + bv.y;
            *(float2*)p0 = v0;
            *(float2*)p1 = v1;
        }
    }
}

// ---------------- launcher ----------------
extern "C" void kernel_launch(void* const* d_in, const int* in_sizes, int n_in,
                              void* d_out, int out_size) {
    (void)in_sizes; (void)n_in; (void)out_size;
    const float* x   = (const float*)d_in[0];
    const int*   wq  = (const int*)d_in[1];
    const float* wsc = (const float*)d_in[2];
    const float* bia = (const float*)d_in[3];
    float* out = (float*)d_out;

    prepass_kernel<<<XB + WB, 256>>>((const float4*)x, wq);

    cudaFuncSetAttribute(gemm_kernel,
                         cudaFuncAttributeMaxDynamicSharedMemorySize, SMEM_TOTAL);
    gemm_kernel<<<NMT * NNT, NTHREADS, SMEM_TOTAL>>>(wsc, bia, out);
}

// round 14
// speedup vs baseline: 1.0111x; 1.0111x over previous
#include <cuda_runtime.h>
#include <cuda_fp16.h>
#include <cstdint>

// Problem shape (fixed)
#define D_M 8192
#define D_N 4096
#define D_K 4096

// GEMM tiling: CTA 128x128, 4 warps (2m x 2n), warp tile 64x64, 2 CTAs/SM
#define TM 128
#define TN 128
#define KS 64                 // K per smem stage
#define KT (D_K / KS)         // 64
#define NMT (D_M / TM)        // 64
#define NNT (D_N / TN)        // 32
#define STAGES 3
#define NTHREADS 128

// fp16 scratch (static device globals: no runtime allocation)
__device__ __half g_A[(size_t)D_M * D_K];   // [M][K]
__device__ __half g_B[(size_t)D_K * D_N];   // [K][N]  (W transposed)

// ---------------- smem layout (per CTA ~99KB so 2 CTAs/SM fit) ----------------
#define A_STAGE (TM * KS * 2)                 // 16384 (128 rows x 128B)
#define B_STAGE (KS * TN * 2)                 // 16384 (64 rows x 256B)
#define SA_OFF 0
#define SB_OFF (STAGES * A_STAGE)             // 49152
#define SCALE_OFF (SB_OFF + STAGES * B_STAGE) // 98304
#define BIAS_OFF (SCALE_OFF + TN * 4)         // 98816
#define SMEM_TOTAL (BIAS_OFF + TN * 4)        // 99328 (x2 = 198656 < 228KB)

// ---------------- helpers ----------------
__device__ __forceinline__ uint32_t smem_u32(const void* p) {
    uint32_t r;
    asm("{ .reg .u64 t; cvta.to.shared.u64 t, %1; cvt.u32.u64 %0, t; }"
        : "=r"(r) : "l"(p));
    return r;
}

__device__ __forceinline__ void cp_async16(uint32_t dst, const void* src) {
    asm volatile("cp.async.cg.shared.global [%0], [%1], 16;"
                 :: "r"(dst), "l"(src));
}

__device__ __forceinline__ void ldsm_x4(uint32_t (&r)[4], uint32_t addr) {
    asm volatile("ldmatrix.sync.aligned.m8n8.x4.shared.b16 {%0,%1,%2,%3}, [%4];"
                 : "=r"(r[0]), "=r"(r[1]), "=r"(r[2]), "=r"(r[3]) : "r"(addr));
}

__device__ __forceinline__ void ldsm_x4_t(uint32_t (&r)[4], uint32_t addr) {
    asm volatile("ldmatrix.sync.aligned.m8n8.x4.trans.shared.b16 {%0,%1,%2,%3}, [%4];"
                 : "=r"(r[0]), "=r"(r[1]), "=r"(r[2]), "=r"(r[3]) : "r"(addr));
}

__device__ __forceinline__ void mma16816(float (&d)[4], const uint32_t (&a)[4],
                                         uint32_t b0, uint32_t b1) {
    asm volatile(
        "mma.sync.aligned.m16n8k16.row.col.f32.f16.f16.f32 "
        "{%0,%1,%2,%3},{%4,%5,%6,%7},{%8,%9},{%0,%1,%2,%3};"
        : "+f"(d[0]), "+f"(d[1]), "+f"(d[2]), "+f"(d[3])
        : "r"(a[0]), "r"(a[1]), "r"(a[2]), "r"(a[3]), "r"(b0), "r"(b1));
}

// ---------------- fused prepass ----------------
// Blocks [0, XB): convert x fp32 -> g_A fp16 (2 float4 per thread)
// Blocks [XB, XB+WB): transpose W [N][K] int32 -> g_B [K][N] fp16
#define XB 16384   // (8192*4096/4 float4) / (256 thr * 2)
#define WB ((D_K / 32) * (D_N / 32))   // 16384

struct alignas(8) H4 { __half2 a, b; };

__global__ void __launch_bounds__(256)
prepass_kernel(const float4* __restrict__ x, const int* __restrict__ w) {
    int b = blockIdx.x;
    if (b < XB) {
        size_t base = (size_t)b * 512 + threadIdx.x;
        float4 v0 = x[base];
        float4 v1 = x[base + 256];
        H4 h0, h1;
        h0.a = __floats2half2_rn(v0.x, v0.y);
        h0.b = __floats2half2_rn(v0.z, v0.w);
        h1.a = __floats2half2_rn(v1.x, v1.y);
        h1.b = __floats2half2_rn(v1.z, v1.w);
        reinterpret_cast<H4*>(g_A)[base] = h0;
        reinterpret_cast<H4*>(g_A)[base + 256] = h1;
    } else {
        __shared__ __half s[32][33];
        int wb = b - XB;
        int tx = threadIdx.x & 31, ty = threadIdx.x >> 5;   // 32 x 8
        int k0 = (wb & (D_K / 32 - 1)) * 32;
        int n0 = (wb / (D_K / 32)) * 32;
#pragma unroll
        for (int r = 0; r < 4; r++) {
            int n = ty + 8 * r;
            s[tx][n] = __int2half_rn(w[(size_t)(n0 + n) * D_K + k0 + tx]);
        }
        __syncthreads();
#pragma unroll
        for (int r = 0; r < 4; r++) {
            int k = ty + 8 * r;
            g_B[(size_t)(k0 + k) * D_N + n0 + tx] = s[k][tx];
        }
    }
}

// ---------------- stage loaders ----------------
// A smem: [m row 0..127][8 chunks of 16B], chunk' = c ^ (m&7)
// B smem: [k row 0..63][16 chunks of 16B], chunk' = (c&~7)|((c&7)^(k&7))
__device__ __forceinline__ void load_stage(int kt, int tid, uint32_t sbase,
                                           const __half* Ag, const __half* Bg) {
    int slot = kt % STAGES;
    uint32_t sa = sbase + SA_OFF + slot * A_STAGE;
    uint32_t sb = sbase + SB_OFF + slot * B_STAGE;
#pragma unroll
    for (int it = 0; it < 8; it++) {
        int idx = tid + it * NTHREADS;       // 0..1023
        int row = idx >> 3, c = idx & 7;
        const void* src = Ag + (size_t)row * D_K + kt * KS + c * 8;
        uint32_t dst = sa + row * 128 + ((c ^ (row & 7)) << 4);
        cp_async16(dst, src);
    }
#pragma unroll
    for (int it = 0; it < 8; it++) {
        int idx = tid + it * NTHREADS;       // 0..1023
        int kr = idx >> 4, c = idx & 15;
        const void* src = Bg + (size_t)(kt * KS + kr) * D_N + c * 8;
        int cs = (c & ~7) | ((c & 7) ^ (kr & 7));
        uint32_t dst = sb + kr * 256 + (cs << 4);
        cp_async16(dst, src);
    }
    asm volatile("cp.async.commit_group;" ::: "memory");
}

// one quarter of a stage (2 A + 2 B cp.asyncs per thread), no commit
__device__ __forceinline__ void load_quarter(int kt, int q, int tid, uint32_t sbase,
                                             const __half* Ag, const __half* Bg) {
    int slot = kt % STAGES;
    uint32_t sa = sbase + SA_OFF + slot * A_STAGE;
    uint32_t sb = sbase + SB_OFF + slot * B_STAGE;
#pragma unroll
    for (int it = 2 * q; it < 2 * q + 2; it++) {
        int idx = tid + it * NTHREADS;
        int row = idx >> 3, c = idx & 7;
        const void* src = Ag + (size_t)row * D_K + kt * KS + c * 8;
        uint32_t dst = sa + row * 128 + ((c ^ (row & 7)) << 4);
        cp_async16(dst, src);
    }
#pragma unroll
    for (int it = 2 * q; it < 2 * q + 2; it++) {
        int idx = tid + it * NTHREADS;
        int kr = idx >> 4, c = idx & 15;
        const void* src = Bg + (size_t)(kt * KS + kr) * D_N + c * 8;
        int cs = (c & ~7) | ((c & 7) ^ (kr & 7));
        uint32_t dst = sb + kr * 256 + (cs << 4);
        cp_async16(dst, src);
    }
}

// ---------------- GEMM kernel ----------------
__global__ void __launch_bounds__(NTHREADS, 2)
gemm_kernel(const float* __restrict__ scale, const float* __restrict__ bias,
            float* __restrict__ out) {
    extern __shared__ __align__(1024) char smem[];
    uint32_t sbase = smem_u32(smem);
    int tid = threadIdx.x, wid = tid >> 5, lane = tid & 31;

    // tile rasterization: supergroups of 8 M-tiles x 32 N-tiles (L2 reuse)
    int bid = blockIdx.x;
    const int G = 8, per = G * NNT;          // 256
    int g = bid / per, r = bid % per;
    int mt = g * G + (r % G);
    int nt = r / G;
    int mbase = mt * TM, nbase = nt * TN;

    const __half* Ag = g_A + (size_t)mbase * D_K;
    const __half* Bg = g_B + nbase;

    // scale/bias preload
    float* ss = (float*)(smem + SCALE_OFF);
    float* bb = (float*)(smem + BIAS_OFF);
    for (int i = tid; i < TN; i += NTHREADS) {
        ss[i] = scale[nbase + i];
        bb[i] = bias[nbase + i];
    }

    // prologue: first STAGES-1 stages in flight
    for (int s = 0; s < STAGES - 1; s++) load_stage(s, tid, sbase, Ag, Bg);

    int wm = (wid & 1) * 64;     // warp m offset (2 m-warps)
    int wn = (wid >> 1) * 64;    // warp n offset (2 n-warps)

    float acc[4][8][4];
#pragma unroll
    for (int i = 0; i < 4; i++)
#pragma unroll
        for (int j = 0; j < 8; j++)
#pragma unroll
            for (int q = 0; q < 4; q++) acc[i][j][q] = 0.f;

    for (int kt = 0; kt < KT; kt++) {
        asm volatile("cp.async.wait_group %0;" :: "n"(STAGES - 2) : "memory");
        __syncthreads();

        int lt = kt + STAGES - 1;
        bool dl = (lt < KT);

        int slot = kt % STAGES;
        uint32_t sa = sbase + SA_OFF + slot * A_STAGE;
        uint32_t sb = sbase + SB_OFF + slot * B_STAGE;

#pragma unroll
        for (int s16 = 0; s16 < 4; s16++) {
            uint32_t a[4][4], b[4][4];
            int arow = wm + (lane & 15);
            int achunk = s16 * 2 + (lane >> 4);
#pragma unroll
            for (int mi = 0; mi < 4; mi++) {
                int rr = arow + mi * 16;
                ldsm_x4(a[mi], sa + rr * 128 + ((achunk ^ (rr & 7)) << 4));
            }
            int bk = s16 * 16 + (lane & 15);
#pragma unroll
            for (int ni = 0; ni < 4; ni++) {
                int chunk = (wn >> 3) + 2 * ni + (lane >> 4);
                int cs = (chunk & ~7) | ((chunk & 7) ^ (bk & 7));
                ldsm_x4_t(b[ni], sb + bk * 256 + (cs << 4));
            }
            // interleave next-stage loads into the LDSM->MMA latency window
            if (dl) load_quarter(lt, s16, tid, sbase, Ag, Bg);
#pragma unroll
            for (int mi = 0; mi < 4; mi++)
#pragma unroll
                for (int ni = 0; ni < 4; ni++) {
                    mma16816(acc[mi][2 * ni],     a[mi], b[ni][0], b[ni][1]);
                    mma16816(acc[mi][2 * ni + 1], a[mi], b[ni][2], b[ni][3]);
                }
        }
        asm volatile("cp.async.commit_group;" ::: "memory");
    }

    // epilogue: scale + bias fused, float2 stores
    int qr = lane >> 2, qc = lane & 3;
#pragma unroll
    for (int mi = 0; mi < 4; mi++) {
        int row0 = mbase + wm + mi * 16 + qr;
#pragma unroll
        for (int nj = 0; nj < 8; nj++) {
            int col = wn + nj * 8 + 2 * qc;
            float2 sc = *(const float2*)(ss + col);
            float2 bv = *(const float2*)(bb + col);
            float* p0 = out + (size_t)row0 * D_N + nbase + col;
            float* p1 = p0 + 8 * (size_t)D_N;
            float2 v0, v1;
            v0.x = acc[mi][nj][0] * sc.x + bv.x;
            v0.y = acc[mi][nj][1] * sc.y + bv.y;
            v1.x = acc[mi][nj][2] * sc.x + bv.x;
            v1.y = acc[mi][nj][3] * sc.y + bv.y;
            *(float2*)p0 = v0;
            *(float2*)p1 = v1;
        }
    }
}

// ---------------- launcher ----------------
extern "C" void kernel_launch(void* const* d_in, const int* in_sizes, int n_in,
                              void* d_out, int out_size) {
    (void)in_sizes; (void)n_in; (void)out_size;
    const float* x   = (const float*)d_in[0];
    const int*   wq  = (const int*)d_in[1];
    const float* wsc = (const float*)d_in[2];
    const float* bia = (const float*)d_in[3];
    float* out = (float*)d_out;

    prepass_kernel<<<XB + WB, 256>>>((const float4*)x, wq);

    cudaFuncSetAttribute(gemm_kernel,
                         cudaFuncAttributeMaxDynamicSharedMemorySize, SMEM_TOTAL);
    gemm_kernel<<<NMT * NNT, NTHREADS, SMEM_TOTAL>>>(wsc, bia, out);
}

// round 15
// speedup vs baseline: 1.0171x; 1.0060x over previous
#include <cuda_runtime.h>
#include <cuda_fp16.h>
#include <cstdint>

// Problem shape (fixed)
#define D_M 8192
#define D_N 4096
#define D_K 4096

// GEMM tiling: CTA 128x128, 4 warps (2m x 2n), warp tile 64x64, 2 CTAs/SM
#define TM 128
#define TN 128
#define KS 64                 // K per smem stage
#define KT (D_K / KS)         // 64
#define NMT (D_M / TM)        // 64
#define NNT (D_N / TN)        // 32
#define STAGES 3
#define NTHREADS 128

// fp16 scratch (static device globals: no runtime allocation)
__device__ __half g_A[(size_t)D_M * D_K];   // [M][K]
__device__ __half g_B[(size_t)D_K * D_N];   // [K][N]  (W transposed)

// ---------------- smem layout (per CTA ~99KB so 2 CTAs/SM fit) ----------------
#define A_STAGE (TM * KS * 2)                 // 16384 (128 rows x 128B)
#define B_STAGE (KS * TN * 2)                 // 16384 (64 rows x 256B)
#define SA_OFF 0
#define SB_OFF (STAGES * A_STAGE)             // 49152
#define SCALE_OFF (SB_OFF + STAGES * B_STAGE) // 98304
#define BIAS_OFF (SCALE_OFF + TN * 4)         // 98816
#define SMEM_TOTAL (BIAS_OFF + TN * 4)        // 99328 (x2 = 198656 < 228KB)

// ---------------- helpers ----------------
__device__ __forceinline__ uint32_t smem_u32(const void* p) {
    uint32_t r;
    asm("{ .reg .u64 t; cvta.to.shared.u64 t, %1; cvt.u32.u64 %0, t; }"
        : "=r"(r) : "l"(p));
    return r;
}

__device__ __forceinline__ void cp_async16(uint32_t dst, const void* src) {
    asm volatile("cp.async.cg.shared.global [%0], [%1], 16;"
                 :: "r"(dst), "l"(src));
}

__device__ __forceinline__ void ldsm_x4(uint32_t (&r)[4], uint32_t addr) {
    asm volatile("ldmatrix.sync.aligned.m8n8.x4.shared.b16 {%0,%1,%2,%3}, [%4];"
                 : "=r"(r[0]), "=r"(r[1]), "=r"(r[2]), "=r"(r[3]) : "r"(addr));
}

__device__ __forceinline__ void ldsm_x4_t(uint32_t (&r)[4], uint32_t addr) {
    asm volatile("ldmatrix.sync.aligned.m8n8.x4.trans.shared.b16 {%0,%1,%2,%3}, [%4];"
                 : "=r"(r[0]), "=r"(r[1]), "=r"(r[2]), "=r"(r[3]) : "r"(addr));
}

__device__ __forceinline__ void mma16816(float (&d)[4], const uint32_t (&a)[4],
                                         uint32_t b0, uint32_t b1) {
    asm volatile(
        "mma.sync.aligned.m16n8k16.row.col.f32.f16.f16.f32 "
        "{%0,%1,%2,%3},{%4,%5,%6,%7},{%8,%9},{%0,%1,%2,%3};"
        : "+f"(d[0]), "+f"(d[1]), "+f"(d[2]), "+f"(d[3])
        : "r"(a[0]), "r"(a[1]), "r"(a[2]), "r"(a[3]), "r"(b0), "r"(b1));
}

// ---------------- fused prepass (streaming hints, 4x unroll) ----------------
// Blocks [0, XB): convert x fp32 -> g_A fp16 (4 float4 per thread)
// Blocks [XB, XB+WB): transpose W [N][K] int32 -> g_B [K][N] fp16
#define XB 8192    // (8192*4096/4 float4) / (256 thr * 4)
#define WB ((D_K / 32) * (D_N / 32))   // 16384

__device__ __forceinline__ unsigned long long pack_h4_f(float4 v) {
    __half2 lo = __floats2half2_rn(v.x, v.y);
    __half2 hi = __floats2half2_rn(v.z, v.w);
    unsigned long long r;
    uint32_t a = *reinterpret_cast<uint32_t*>(&lo);
    uint32_t b = *reinterpret_cast<uint32_t*>(&hi);
    r = ((unsigned long long)b << 32) | a;
    return r;
}

__global__ void __launch_bounds__(256)
prepass_kernel(const float4* __restrict__ x, const int* __restrict__ w) {
    int b = blockIdx.x;
    if (b < XB) {
        size_t base = (size_t)b * 1024 + threadIdx.x;
        float4 v0 = __ldcs(x + base);
        float4 v1 = __ldcs(x + base + 256);
        float4 v2 = __ldcs(x + base + 512);
        float4 v3 = __ldcs(x + base + 768);
        unsigned long long* dst = reinterpret_cast<unsigned long long*>(g_A);
        __stcs(dst + base,       pack_h4_f(v0));
        __stcs(dst + base + 256, pack_h4_f(v1));
        __stcs(dst + base + 512, pack_h4_f(v2));
        __stcs(dst + base + 768, pack_h4_f(v3));
    } else {
        __shared__ __half s[32][33];
        int wb = b - XB;
        int tx = threadIdx.x & 31, ty = threadIdx.x >> 5;   // 32 x 8
        int k0 = (wb & (D_K / 32 - 1)) * 32;
        int n0 = (wb / (D_K / 32)) * 32;
#pragma unroll
        for (int r = 0; r < 4; r++) {
            int n = ty + 8 * r;
            s[tx][n] = __int2half_rn(__ldcs(&w[(size_t)(n0 + n) * D_K + k0 + tx]));
        }
        __syncthreads();
#pragma unroll
        for (int r = 0; r < 4; r++) {
            int k = ty + 8 * r;
            unsigned short hv = *reinterpret_cast<unsigned short*>(&s[k][tx]);
            __stcs(reinterpret_cast<unsigned short*>(&g_B[(size_t)(k0 + k) * D_N + n0 + tx]), hv);
        }
    }
}

// ---------------- stage loaders ----------------
// A smem: [m row 0..127][8 chunks of 16B], chunk' = c ^ (m&7)
// B smem: [k row 0..63][16 chunks of 16B], chunk' = (c&~7)|((c&7)^(k&7))
__device__ __forceinline__ void load_stage(int kt, int tid, uint32_t sbase,
                                           const __half* Ag, const __half* Bg) {
    int slot = kt % STAGES;
    uint32_t sa = sbase + SA_OFF + slot * A_STAGE;
    uint32_t sb = sbase + SB_OFF + slot * B_STAGE;
#pragma unroll
    for (int it = 0; it < 8; it++) {
        int idx = tid + it * NTHREADS;       // 0..1023
        int row = idx >> 3, c = idx & 7;
        const void* src = Ag + (size_t)row * D_K + kt * KS + c * 8;
        uint32_t dst = sa + row * 128 + ((c ^ (row & 7)) << 4);
        cp_async16(dst, src);
    }
#pragma unroll
    for (int it = 0; it < 8; it++) {
        int idx = tid + it * NTHREADS;       // 0..1023
        int kr = idx >> 4, c = idx & 15;
        const void* src = Bg + (size_t)(kt * KS + kr) * D_N + c * 8;
        int cs = (c & ~7) | ((c & 7) ^ (kr & 7));
        uint32_t dst = sb + kr * 256 + (cs << 4);
        cp_async16(dst, src);
    }
    asm volatile("cp.async.commit_group;" ::: "memory");
}

// one quarter of a stage (2 A + 2 B cp.asyncs per thread), no commit
__device__ __forceinline__ void load_quarter(int kt, int q, int tid, uint32_t sbase,
                                             const __half* Ag, const __half* Bg) {
    int slot = kt % STAGES;
    uint32_t sa = sbase + SA_OFF + slot * A_STAGE;
    uint32_t sb = sbase + SB_OFF + slot * B_STAGE;
#pragma unroll
    for (int it = 2 * q; it < 2 * q + 2; it++) {
        int idx = tid + it * NTHREADS;
        int row = idx >> 3, c = idx & 7;
        const void* src = Ag + (size_t)row * D_K + kt * KS + c * 8;
        uint32_t dst = sa + row * 128 + ((c ^ (row & 7)) << 4);
        cp_async16(dst, src);
    }
#pragma unroll
    for (int it = 2 * q; it < 2 * q + 2; it++) {
        int idx = tid + it * NTHREADS;
        int kr = idx >> 4, c = idx & 15;
        const void* src = Bg + (size_t)(kt * KS + kr) * D_N + c * 8;
        int cs = (c & ~7) | ((c & 7) ^ (kr & 7));
        uint32_t dst = sb + kr * 256 + (cs << 4);
        cp_async16(dst, src);
    }
}

// ---------------- GEMM kernel (R12 structure, unchanged) ----------------
__global__ void __launch_bounds__(NTHREADS, 2)
gemm_kernel(const float* __restrict__ scale, const float* __restrict__ bias,
            float* __restrict__ out) {
    extern __shared__ __align__(1024) char smem[];
    uint32_t sbase = smem_u32(smem);
    int tid = threadIdx.x, wid = tid >> 5, lane = tid & 31;

    // tile rasterization: supergroups of 8 M-tiles x 32 N-tiles (L2 reuse)
    int bid = blockIdx.x;
    const int G = 8, per = G * NNT;          // 256
    int g = bid / per, r = bid % per;
    int mt = g * G + (r % G);
    int nt = r / G;
    int mbase = mt * TM, nbase = nt * TN;

    const __half* Ag = g_A + (size_t)mbase * D_K;
    const __half* Bg = g_B + nbase;

    // scale/bias preload
    float* ss = (float*)(smem + SCALE_OFF);
    float* bb = (float*)(smem + BIAS_OFF);
    for (int i = tid; i < TN; i += NTHREADS) {
        ss[i] = scale[nbase + i];
        bb[i] = bias[nbase + i];
    }

    // prologue: first STAGES-1 stages in flight
    for (int s = 0; s < STAGES - 1; s++) load_stage(s, tid, sbase, Ag, Bg);

    int wm = (wid & 1) * 64;     // warp m offset (2 m-warps)
    int wn = (wid >> 1) * 64;    // warp n offset (2 n-warps)

    float acc[4][8][4];
#pragma unroll
    for (int i = 0; i < 4; i++)
#pragma unroll
        for (int j = 0; j < 8; j++)
#pragma unroll
            for (int q = 0; q < 4; q++) acc[i][j][q] = 0.f;

    for (int kt = 0; kt < KT; kt++) {
        asm volatile("cp.async.wait_group %0;" :: "n"(STAGES - 2) : "memory");
        __syncthreads();

        int lt = kt + STAGES - 1;
        bool dl = (lt < KT);

        int slot = kt % STAGES;
        uint32_t sa = sbase + SA_OFF + slot * A_STAGE;
        uint32_t sb = sbase + SB_OFF + slot * B_STAGE;

#pragma unroll
        for (int s16 = 0; s16 < 4; s16++) {
            uint32_t a[4][4], b[4][4];
            int arow = wm + (lane & 15);
            int achunk = s16 * 2 + (lane >> 4);
#pragma unroll
            for (int mi = 0; mi < 4; mi++) {
                int rr = arow + mi * 16;
                ldsm_x4(a[mi], sa + rr * 128 + ((achunk ^ (rr & 7)) << 4));
            }
            int bk = s16 * 16 + (lane & 15);
#pragma unroll
            for (int ni = 0; ni < 4; ni++) {
                int chunk = (wn >> 3) + 2 * ni + (lane >> 4);
                int cs = (chunk & ~7) | ((chunk & 7) ^ (bk & 7));
                ldsm_x4_t(b[ni], sb + bk * 256 + (cs << 4));
            }
            // interleave next-stage loads into the LDSM->MMA latency window
            if (dl) load_quarter(lt, s16, tid, sbase, Ag, Bg);
#pragma unroll
            for (int mi = 0; mi < 4; mi++)
#pragma unroll
                for (int ni = 0; ni < 4; ni++) {
                    mma16816(acc[mi][2 * ni],     a[mi], b[ni][0], b[ni][1]);
                    mma16816(acc[mi][2 * ni + 1], a[mi], b[ni][2], b[ni][3]);
                }
        }
        asm volatile("cp.async.commit_group;" ::: "memory");
    }

    // epilogue: scale + bias fused, float2 stores
    int qr = lane >> 2, qc = lane & 3;
#pragma unroll
    for (int mi = 0; mi < 4; mi++) {
        int row0 = mbase + wm + mi * 16 + qr;
#pragma unroll
        for (int nj = 0; nj < 8; nj++) {
            int col = wn + nj * 8 + 2 * qc;
            float2 sc = *(const float2*)(ss + col);
            float2 bv = *(const float2*)(bb + col);
            float* p0 = out + (size_t)row0 * D_N + nbase + col;
            float* p1 = p0 + 8 * (size_t)D_N;
            float2 v0, v1;
            v0.x = acc[mi][nj][0] * sc.x + bv.x;
            v0.y = acc[mi][nj][1] * sc.y + bv.y;
            v1.x = acc[mi][nj][2] * sc.x + bv.x;
            v1.y = acc[mi][nj][3] * sc.y + bv.y;
            *(float2*)p0 = v0;
            *(float2*)p1 = v1;
        }
    }
}

// ---------------- launcher ----------------
extern "C" void kernel_launch(void* const* d_in, const int* in_sizes, int n_in,
                              void* d_out, int out_size) {
    (void)in_sizes; (void)n_in; (void)out_size;
    const float* x   = (const float*)d_in[0];
    const int*   wq  = (const int*)d_in[1];
    const float* wsc = (const float*)d_in[2];
    const float* bia = (const float*)d_in[3];
    float* out = (float*)d_out;

    prepass_kernel<<<XB + WB, 256>>>((const float4*)x, wq);

    cudaFuncSetAttribute(gemm_kernel,
                         cudaFuncAttributeMaxDynamicSharedMemorySize, SMEM_TOTAL);
    gemm_kernel<<<NMT * NNT, NTHREADS, SMEM_TOTAL>>>(wsc, bia, out);
}

// round 17
// speedup vs baseline: 1.0209x; 1.0037x over previous
#include <cuda_runtime.h>
#include <cuda_fp16.h>
#include <cstdint>

// Problem shape (fixed)
#define D_M 8192
#define D_N 4096
#define D_K 4096

// GEMM tiling: CTA 128x128, 4 warps (2m x 2n), warp tile 64x64, 2 CTAs/SM
#define TM 128
#define TN 128
#define KS 64                 // K per smem stage
#define KT (D_K / KS)         // 64
#define NMT (D_M / TM)        // 64
#define NNT (D_N / TN)        // 32
#define STAGES 3
#define NTHREADS 128

// fp16 scratch (static device globals: no runtime allocation)
__device__ __half g_A[(size_t)D_M * D_K];   // [M][K]
__device__ __half g_B[(size_t)D_K * D_N];   // [K][N]  (W transposed)

// ---------------- smem layout (per CTA ~99KB so 2 CTAs/SM fit) ----------------
#define A_STAGE (TM * KS * 2)                 // 16384 (128 rows x 128B)
#define B_STAGE (KS * TN * 2)                 // 16384 (64 rows x 256B)
#define SA_OFF 0
#define SB_OFF (STAGES * A_STAGE)             // 49152
#define SCALE_OFF (SB_OFF + STAGES * B_STAGE) // 98304
#define BIAS_OFF (SCALE_OFF + TN * 4)         // 98816
#define SMEM_TOTAL (BIAS_OFF + TN * 4)        // 99328 (x2 = 198656 < 228KB)

// ---------------- helpers ----------------
__device__ __forceinline__ uint32_t smem_u32(const void* p) {
    uint32_t r;
    asm("{ .reg .u64 t; cvta.to.shared.u64 t, %1; cvt.u32.u64 %0, t; }"
        : "=r"(r) : "l"(p));
    return r;
}

__device__ __forceinline__ void cp_async16(uint32_t dst, const void* src) {
    asm volatile("cp.async.cg.shared.global [%0], [%1], 16;"
                 :: "r"(dst), "l"(src));
}

__device__ __forceinline__ void ldsm_x4(uint32_t (&r)[4], uint32_t addr) {
    asm volatile("ldmatrix.sync.aligned.m8n8.x4.shared.b16 {%0,%1,%2,%3}, [%4];"
                 : "=r"(r[0]), "=r"(r[1]), "=r"(r[2]), "=r"(r[3]) : "r"(addr));
}

__device__ __forceinline__ void ldsm_x4_t(uint32_t (&r)[4], uint32_t addr) {
    asm volatile("ldmatrix.sync.aligned.m8n8.x4.trans.shared.b16 {%0,%1,%2,%3}, [%4];"
                 : "=r"(r[0]), "=r"(r[1]), "=r"(r[2]), "=r"(r[3]) : "r"(addr));
}

__device__ __forceinline__ void mma16816(float (&d)[4], const uint32_t (&a)[4],
                                         uint32_t b0, uint32_t b1) {
    asm volatile(
        "mma.sync.aligned.m16n8k16.row.col.f32.f16.f16.f32 "
        "{%0,%1,%2,%3},{%4,%5,%6,%7},{%8,%9},{%0,%1,%2,%3};"
        : "+f"(d[0]), "+f"(d[1]), "+f"(d[2]), "+f"(d[3])
        : "r"(a[0]), "r"(a[1]), "r"(a[2]), "r"(a[3]), "r"(b0), "r"(b1));
}

// ---------------- fused prepass (streaming hints, coalesced W stores) ----------------
// Blocks [0, XB): convert x fp32 -> g_A fp16 (4 float4 per thread)
// Blocks [XB, XB+WB): transpose W [N][K] int32 -> g_B [K][N] fp16, 64n x 32k tiles
#define XB 8192    // (8192*4096/4 float4) / (256 thr * 4)
#define WB ((D_K / 32) * (D_N / 64))   // 8192

__device__ __forceinline__ unsigned long long pack_h4_f(float4 v) {
    __half2 lo = __floats2half2_rn(v.x, v.y);
    __half2 hi = __floats2half2_rn(v.z, v.w);
    uint32_t a = *reinterpret_cast<uint32_t*>(&lo);
    uint32_t b = *reinterpret_cast<uint32_t*>(&hi);
    return ((unsigned long long)b << 32) | a;
}

__global__ void __launch_bounds__(256)
prepass_kernel(const float4* __restrict__ x, const int* __restrict__ w) {
    int b = blockIdx.x;
    if (b < XB) {
        size_t base = (size_t)b * 1024 + threadIdx.x;
        float4 v0 = __ldcs(x + base);
        float4 v1 = __ldcs(x + base + 256);
        float4 v2 = __ldcs(x + base + 512);
        float4 v3 = __ldcs(x + base + 768);
        unsigned long long* dst = reinterpret_cast<unsigned long long*>(g_A);
        __stcs(dst + base,       pack_h4_f(v0));
        __stcs(dst + base + 256, pack_h4_f(v1));
        __stcs(dst + base + 512, pack_h4_f(v2));
        __stcs(dst + base + 768, pack_h4_f(v3));
    } else {
        // transpose tile: 64 n-rows x 32 k-cols -> writes of 128B per k-row
        // pad 66 (132B row stride): 4B-aligned for uint32 access, odd word stride
        __shared__ __half s[32][66];         // [k][n]
        int wb = b - XB;
        int tid = threadIdx.x;
        int k0 = (wb & (D_K / 32 - 1)) * 32;
        int n0 = (wb / (D_K / 32)) * 64;
        // load: 64*32 = 2048 elems, 8 per thread; lanes sweep k (coalesced 128B)
#pragma unroll
        for (int it = 0; it < 8; it++) {
            int idx = tid + it * 256;        // 0..2047
            int n = idx >> 5, kk = idx & 31;
            s[kk][n] = __int2half_rn(__ldcs(&w[(size_t)(n0 + n) * D_K + k0 + kk]));
        }
        __syncthreads();
        // store: 32 k-rows x 32 uint32 (2 halves each); lanes sweep n (coalesced 128B)
#pragma unroll
        for (int it = 0; it < 4; it++) {
            int idx = tid + it * 256;        // 0..1023
            int k = idx >> 5, j = idx & 31;
            uint32_t v = *reinterpret_cast<uint32_t*>(&s[k][2 * j]);
            __stcs(reinterpret_cast<uint32_t*>(&g_B[(size_t)(k0 + k) * D_N + n0 + 2 * j]), v);
        }
    }
}

// ---------------- stage loaders ----------------
// A smem: [m row 0..127][8 chunks of 16B], chunk' = c ^ (m&7)
// B smem: [k row 0..63][16 chunks of 16B], chunk' = (c&~7)|((c&7)^(k&7))
__device__ __forceinline__ void load_stage(int kt, int tid, uint32_t sbase,
                                           const __half* Ag, const __half* Bg) {
    int slot = kt % STAGES;
    uint32_t sa = sbase + SA_OFF + slot * A_STAGE;
    uint32_t sb = sbase + SB_OFF + slot * B_STAGE;
#pragma unroll
    for (int it = 0; it < 8; it++) {
        int idx = tid + it * NTHREADS;       // 0..1023
        int row = idx >> 3, c = idx & 7;
        const void* src = Ag + (size_t)row * D_K + kt * KS + c * 8;
        uint32_t dst = sa + row * 128 + ((c ^ (row & 7)) << 4);
        cp_async16(dst, src);
    }
#pragma unroll
    for (int it = 0; it < 8; it++) {
        int idx = tid + it * NTHREADS;       // 0..1023
        int kr = idx >> 4, c = idx & 15;
        const void* src = Bg + (size_t)(kt * KS + kr) * D_N + c * 8;
        int cs = (c & ~7) | ((c & 7) ^ (kr & 7));
        uint32_t dst = sb + kr * 256 + (cs << 4);
        cp_async16(dst, src);
    }
    asm volatile("cp.async.commit_group;" ::: "memory");
}

// one quarter of a stage (2 A + 2 B cp.asyncs per thread), no commit
__device__ __forceinline__ void load_quarter(int kt, int q, int tid, uint32_t sbase,
                                             const __half* Ag, const __half* Bg) {
    int slot = kt % STAGES;
    uint32_t sa = sbase + SA_OFF + slot * A_STAGE;
    uint32_t sb = sbase + SB_OFF + slot * B_STAGE;
#pragma unroll
    for (int it = 2 * q; it < 2 * q + 2; it++) {
        int idx = tid + it * NTHREADS;
        int row = idx >> 3, c = idx & 7;
        const void* src = Ag + (size_t)row * D_K + kt * KS + c * 8;
        uint32_t dst = sa + row * 128 + ((c ^ (row & 7)) << 4);
        cp_async16(dst, src);
    }
#pragma unroll
    for (int it = 2 * q; it < 2 * q + 2; it++) {
        int idx = tid + it * NTHREADS;
        int kr = idx >> 4, c = idx & 15;
        const void* src = Bg + (size_t)(kt * KS + kr) * D_N + c * 8;
        int cs = (c & ~7) | ((c & 7) ^ (kr & 7));
        uint32_t dst = sb + kr * 256 + (cs << 4);
        cp_async16(dst, src);
    }
}

// ---------------- GEMM kernel (R12 structure, unchanged) ----------------
__global__ void __launch_bounds__(NTHREADS, 2)
gemm_kernel(const float* __restrict__ scale, const float* __restrict__ bias,
            float* __restrict__ out) {
    extern __shared__ __align__(1024) char smem[];
    uint32_t sbase = smem_u32(smem);
    int tid = threadIdx.x, wid = tid >> 5, lane = tid & 31;

    // tile rasterization: supergroups of 8 M-tiles x 32 N-tiles (L2 reuse)
    int bid = blockIdx.x;
    const int G = 8, per = G * NNT;          // 256
    int g = bid / per, r = bid % per;
    int mt = g * G + (r % G);
    int nt = r / G;
    int mbase = mt * TM, nbase = nt * TN;

    const __half* Ag = g_A + (size_t)mbase * D_K;
    const __half* Bg = g_B + nbase;

    // scale/bias preload
    float* ss = (float*)(smem + SCALE_OFF);
    float* bb = (float*)(smem + BIAS_OFF);
    for (int i = tid; i < TN; i += NTHREADS) {
        ss[i] = scale[nbase + i];
        bb[i] = bias[nbase + i];
    }

    // prologue: first STAGES-1 stages in flight
    for (int s = 0; s < STAGES - 1; s++) load_stage(s, tid, sbase, Ag, Bg);

    int wm = (wid & 1) * 64;     // warp m offset (2 m-warps)
    int wn = (wid >> 1) * 64;    // warp n offset (2 n-warps)

    float acc[4][8][4];
#pragma unroll
    for (int i = 0; i < 4; i++)
#pragma unroll
        for (int j = 0; j < 8; j++)
#pragma unroll
            for (int q = 0; q < 4; q++) acc[i][j][q] = 0.f;

    for (int kt = 0; kt < KT; kt++) {
        asm volatile("cp.async.wait_group %0;" :: "n"(STAGES - 2) : "memory");
        __syncthreads();

        int lt = kt + STAGES - 1;
        bool dl = (lt < KT);

        int slot = kt % STAGES;
        uint32_t sa = sbase + SA_OFF + slot * A_STAGE;
        uint32_t sb = sbase + SB_OFF + slot * B_STAGE;

#pragma unroll
        for (int s16 = 0; s16 < 4; s16++) {
            uint32_t a[4][4], b[4][4];
            int arow = wm + (lane & 15);
            int achunk = s16 * 2 + (lane >> 4);
#pragma unroll
            for (int mi = 0; mi < 4; mi++) {
                int rr = arow + mi * 16;
                ldsm_x4(a[mi], sa + rr * 128 + ((achunk ^ (rr & 7)) << 4));
            }
            int bk = s16 * 16 + (lane & 15);
#pragma unroll
            for (int ni = 0; ni < 4; ni++) {
                int chunk = (wn >> 3) + 2 * ni + (lane >> 4);
                int cs = (chunk & ~7) | ((chunk & 7) ^ (bk & 7));
                ldsm_x4_t(b[ni], sb + bk * 256 + (cs << 4));
            }
            // interleave next-stage loads into the LDSM->MMA latency window
            if (dl) load_quarter(lt, s16, tid, sbase, Ag, Bg);
#pragma unroll
            for (int mi = 0; mi < 4; mi++)
#pragma unroll
                for (int ni = 0; ni < 4; ni++) {
                    mma16816(acc[mi][2 * ni],     a[mi], b[ni][0], b[ni][1]);
                    mma16816(acc[mi][2 * ni + 1], a[mi], b[ni][2], b[ni][3]);
                }
        }
        asm volatile("cp.async.commit_group;" ::: "memory");
    }

    // epilogue: scale + bias fused, float2 stores
    int qr = lane >> 2, qc = lane & 3;
#pragma unroll
    for (int mi = 0; mi < 4; mi++) {
        int row0 = mbase + wm + mi * 16 + qr;
#pragma unroll
        for (int nj = 0; nj < 8; nj++) {
            int col = wn + nj * 8 + 2 * qc;
            float2 sc = *(const float2*)(ss + col);
            float2 bv = *(const float2*)(bb + col);
            float* p0 = out + (size_t)row0 * D_N + nbase + col;
            float* p1 = p0 + 8 * (size_t)D_N;
            float2 v0, v1;
            v0.x = acc[mi][nj][0] * sc.x + bv.x;
            v0.y = acc[mi][nj][1] * sc.y + bv.y;
            v1.x = acc[mi][nj][2] * sc.x + bv.x;
            v1.y = acc[mi][nj][3] * sc.y + bv.y;
            *(float2*)p0 = v0;
            *(float2*)p1 = v1;
        }
    }
}

// ---------------- launcher ----------------
extern "C" void kernel_launch(void* const* d_in, const int* in_sizes, int n_in,
                              void* d_out, int out_size) {
    (void)in_sizes; (void)n_in; (void)out_size;
    const float* x   = (const float*)d_in[0];
    const int*   wq  = (const int*)d_in[1];
    const float* wsc = (const float*)d_in[2];
    const float* bia = (const float*)d_in[3];
    float* out = (float*)d_out;

    prepass_kernel<<<XB + WB, 256>>>((const float4*)x, wq);

    cudaFuncSetAttribute(gemm_kernel,
                         cudaFuncAttributeMaxDynamicSharedMemorySize, SMEM_TOTAL);
    gemm_kernel<<<NMT * NNT, NTHREADS, SMEM_TOTAL>>>(wsc, bia, out);
}